// round 14
// baseline (speedup 1.0000x reference)
#include <cuda_runtime.h>
#include <cuda_bf16.h>
#include <cuda_fp16.h>
#include <math.h>

#define BB   8
#define QQ   2048
#define KK2  2048
#define FF   512
#define FVV  512
#define NTHREADS 256

// ---------------- scratch (device globals; no runtime allocation) ----------------
// bf16 A-blob (64x64): [ks4][mf4][lane32][4 b32]
// bf16/fp16 B-blob (64k x 64n): [ks4][nf8][lane32][2 b32]
__device__ __align__(16) unsigned g_Qpb[4194304];     // (b, qt32, ft8) bf16 A-blobs   16.8MB
__device__ __align__(16) unsigned g_Kpb[4194304];     // (b, kt32, ft8) bf16 B-blobs   16.8MB
__device__ __align__(16) unsigned g_Vph[4194304];     // (b, fvt8, kt32) fp16 B-blobs  16.8MB
__device__ __align__(16) __nv_bfloat16 g_E[33554432]; // exp(logits) row-major         67MB
__device__ __align__(16) unsigned g_pam[1048576];     // attn mask, 1 bit/elem (64 w/row) 4.2MB
__device__ __align__(16) unsigned g_pal[1048576];     // alibi mask, 1 bit/elem           4.2MB
__device__ float g_linv[BB*QQ];
__device__ int   g_mask_is_int32;

// ---------------- helpers ----------------
__device__ __forceinline__ void mma_bf16(float c[4], const unsigned* a, const unsigned* b){
    asm volatile("mma.sync.aligned.m16n8k16.row.col.f32.bf16.bf16.f32 "
        "{%0,%1,%2,%3}, {%4,%5,%6,%7}, {%8,%9}, {%0,%1,%2,%3};"
        : "+f"(c[0]), "+f"(c[1]), "+f"(c[2]), "+f"(c[3])
        : "r"(a[0]), "r"(a[1]), "r"(a[2]), "r"(a[3]), "r"(b[0]), "r"(b[1]));
}
__device__ __forceinline__ void mma_fp16(float c[4], const unsigned* a, const unsigned* b){
    asm volatile("mma.sync.aligned.m16n8k16.row.col.f32.f16.f16.f32 "
        "{%0,%1,%2,%3}, {%4,%5,%6,%7}, {%8,%9}, {%0,%1,%2,%3};"
        : "+f"(c[0]), "+f"(c[1]), "+f"(c[2]), "+f"(c[3])
        : "r"(a[0]), "r"(a[1]), "r"(a[2]), "r"(a[3]), "r"(b[0]), "r"(b[1]));
}
// exp on the FMA pipe: 2^(x*log2e), deg-5 poly (rel err ~2e-7 for |x| < 15)
__device__ __forceinline__ float fexp(float x){
    float t = x * 1.4426950408889634f;
    float r = rintf(t);
    float f = t - r;
    float p = 1.3333558146428443e-3f;
    p = fmaf(p, f, 9.618129107628477e-3f);
    p = fmaf(p, f, 5.550410866482158e-2f);
    p = fmaf(p, f, 2.402265069591007e-1f);
    p = fmaf(p, f, 6.931471805599453e-1f);
    p = fmaf(p, f, 1.0f);
    return __int_as_float(((int)r + 127) << 23) * p;
}
// rsqrt on FMA pipe, 2 Newton steps (~1e-6 rel)
__device__ __forceinline__ float frsqrt2(float x){
    float y = __int_as_float(0x5f3759df - (__float_as_int(x) >> 1));
    y = y * (1.5f - 0.5f * x * y * y);
    y = y * (1.5f - 0.5f * x * y * y);
    return y;
}

// ---------------- mask dtype probe ----------------
__global__ void detect_mask_kernel(const unsigned char* am){
    unsigned nz = 0;
    #pragma unroll 8
    for (int i = 0; i < 1024; i++) nz |= am[4*i+1] | am[4*i+2] | am[4*i+3];
    g_mask_is_int32 = (nz == 0u) ? 1 : 0;
}

// ---------------- prep Q -> bf16 A-fragment blobs ----------------
__global__ void __launch_bounds__(NTHREADS) prep_qb_kernel(const float* __restrict__ q){
    int w = blockIdx.x * 8 + (threadIdx.x >> 5);
    int lane = threadIdx.x & 31, g = lane >> 2, t = lane & 3;
    int mf = w & 3, ks = (w>>2)&3, ft = (w>>4)&7, qt = (w>>7)&31, b = w>>12;
    unsigned rr[4];
    #pragma unroll
    for (int rh = 0; rh < 2; rh++){
        int row = qt*64 + mf*16 + g + 8*rh;
        const float* qp = q + ((size_t)(b*QQ + row))*FF + ft*64 + ks*16 + 2*t;
        float2 x0 = *(const float2*)qp;
        float2 x1 = *(const float2*)(qp + 8);
        __nv_bfloat162 h0 = __floats2bfloat162_rn(x0.x, x0.y);
        __nv_bfloat162 h1 = __floats2bfloat162_rn(x1.x, x1.y);
        rr[rh]   = *(unsigned*)&h0;
        rr[rh+2] = *(unsigned*)&h1;
    }
    size_t blob = ((size_t)((b*32 + qt)*8 + ft))*2048;
    *(uint4*)(g_Qpb + blob + ((ks*4 + mf)*32 + lane)*4) = make_uint4(rr[0],rr[1],rr[2],rr[3]);
}

// ---------------- prep K -> bf16 B-fragment blobs ----------------
__global__ void __launch_bounds__(NTHREADS) prep_kb_kernel(const float* __restrict__ k){
    int w = blockIdx.x * 8 + (threadIdx.x >> 5);
    int lane = threadIdx.x & 31, g = lane >> 2, t = lane & 3;
    int nf = w & 7, ks = (w>>3)&3, ft = (w>>5)&7, kt = (w>>8)&31, b = w>>13;
    int n = kt*64 + nf*8 + g;
    const float* kp = k + ((size_t)(b*KK2 + n))*FF + ft*64 + ks*16 + 2*t;
    float2 x0 = *(const float2*)kp;
    float2 x1 = *(const float2*)(kp + 8);
    __nv_bfloat162 h0 = __floats2bfloat162_rn(x0.x, x0.y);
    __nv_bfloat162 h1 = __floats2bfloat162_rn(x1.x, x1.y);
    size_t blob = ((size_t)((b*32 + kt)*8 + ft))*2048;
    *(uint2*)(g_Kpb + blob + ((ks*8 + nf)*32 + lane)*2) =
        make_uint2(*(unsigned*)&h0, *(unsigned*)&h1);
}

// ---------------- prep V -> fp16 B-fragment blobs (smem transpose, coalesced) ----------------
__global__ void __launch_bounds__(NTHREADS) prep_vh_kernel(const float* __restrict__ v){
    __shared__ float ts[64][68];
    int bx = blockIdx.x;                 // 8 fb x 32 kt x 8 b
    int fb = bx & 7, kt = (bx>>3) & 31, b = bx >> 8;
    int tid = threadIdx.x;
    {
        int fc = (tid & 15) * 4;
        int k0 = tid >> 4;
        #pragma unroll
        for (int it = 0; it < 4; it++){
            int kk = it*16 + k0;
            float4 x = *(const float4*)(v + ((size_t)(b*KK2 + kt*64 + kk))*FVV + fb*64 + fc);
            *(float4*)&ts[kk][fc] = x;
        }
    }
    __syncthreads();
    int lane = tid & 31, g = lane >> 2, t = lane & 3;
    int nf = tid >> 5;
    int n = nf*8 + g;
    unsigned* dst = g_Vph + ((size_t)((b*8 + fb)*32 + kt))*2048;
    #pragma unroll
    for (int ks = 0; ks < 4; ks++){
        __half2 w0 = __floats2half2_rn(ts[ks*16 + 2*t    ][n], ts[ks*16 + 2*t + 1][n]);
        __half2 w1 = __floats2half2_rn(ts[ks*16 + 2*t + 8][n], ts[ks*16 + 2*t + 9][n]);
        *(uint2*)(dst + ((ks*8 + nf)*32 + lane)*2) =
            make_uint2(*(unsigned*)&w0, *(unsigned*)&w1);
    }
}

// ---------------- pass1 (32-row q-tiles, 2 CTAs/SM): S=QK^T*scale; E=exp(S); linv; mask pack ----------------
__global__ void __launch_bounds__(NTHREADS, 2) pass1_kernel(
    const unsigned char* __restrict__ am, const unsigned char* __restrict__ al)
{
    extern __shared__ unsigned smem_u[];
    unsigned* smQ = smem_u;                    // 8192 words = 32KB
    float* l_s = (float*)(smem_u + 8192);      // 8 warps * 32 rows

    int tid = threadIdx.x, lane = tid & 31, wc = tid >> 5;
    int g = lane >> 2, t = lane & 3;
    int b = blockIdx.x >> 6, qt = blockIdx.x & 63;
    const int qt64 = qt >> 1, mb = (qt & 1) * 2;
    const float SCALE = 0.044194173824159216f;  // 1/sqrt(512)
    const int m32 = g_mask_is_int32;

    // ---- pack masks for this CTA's 32 rows (consumed by pass2) ----
    // thread: row = tid>>3, col chunk (tid&7)*256..+255 -> 8 packed words per mask
    {
        int r = tid >> 3, ch = tid & 7;
        size_t rbase = ((size_t)(b*QQ + qt*32 + r))*KK2 + ch*256;
        unsigned* pam_out = g_pam + ((size_t)(b*QQ + qt*32 + r))*64 + ch*8;
        unsigned* pal_out = g_pal + ((size_t)(b*QQ + qt*32 + r))*64 + ch*8;
        if (m32){
            const uint4* ap = (const uint4*)((const int*)am + rbase);
            const uint4* lp = (const uint4*)((const int*)al + rbase);
            #pragma unroll 1
            for (int w = 0; w < 8; w++){
                unsigned pa = 0, pl = 0;
                #pragma unroll
                for (int i = 0; i < 8; i++){
                    uint4 xa = ap[w*8 + i];
                    uint4 xl = lp[w*8 + i];
                    pa |= (xa.x&1u)<<(4*i) | (xa.y&1u)<<(4*i+1)
                        | (xa.z&1u)<<(4*i+2) | (xa.w&1u)<<(4*i+3);
                    pl |= (xl.x&1u)<<(4*i) | (xl.y&1u)<<(4*i+1)
                        | (xl.z&1u)<<(4*i+2) | (xl.w&1u)<<(4*i+3);
                }
                pam_out[w] = pa; pal_out[w] = pl;
            }
        } else {
            const uint4* ap = (const uint4*)(am + rbase);
            const uint4* lp = (const uint4*)(al + rbase);
            #pragma unroll 1
            for (int w = 0; w < 8; w++){
                unsigned pa = 0, pl = 0;
                #pragma unroll
                for (int h = 0; h < 2; h++){
                    uint4 xa = ap[w*2 + h];
                    uint4 xl = lp[w*2 + h];
                    // bytes(0/1) -> 4 bits via multiply-gather
                    pa |= ((((xa.x&0x01010101u)*0x10204080u)>>28) << (16*h))
                        | ((((xa.y&0x01010101u)*0x10204080u)>>28) << (16*h+4))
                        | ((((xa.z&0x01010101u)*0x10204080u)>>28) << (16*h+8))
                        | ((((xa.w&0x01010101u)*0x10204080u)>>28) << (16*h+12));
                    pl |= ((((xl.x&0x01010101u)*0x10204080u)>>28) << (16*h))
                        | ((((xl.y&0x01010101u)*0x10204080u)>>28) << (16*h+4))
                        | ((((xl.z&0x01010101u)*0x10204080u)>>28) << (16*h+8))
                        | ((((xl.w&0x01010101u)*0x10204080u)>>28) << (16*h+12));
                }
                pam_out[w] = pa; pal_out[w] = pl;
            }
        }
    }

    {
        const unsigned* base = g_Qpb + ((size_t)((b*32 + qt64)*8))*2048;
        #pragma unroll
        for (int i = 0; i < 8; i++){
            int j = tid + 256*i;
            int lj = j & 31, mf = (j>>5)&1, ks = (j>>6)&3, ft = j>>8;
            *(uint4*)(smQ + ((size_t)j)*4) =
                *(const uint4*)(base + ft*2048 + ((ks*4 + mb + mf)*32 + lj)*4);
        }
    }
    __syncthreads();

    float rsl[2][2];
    rsl[0][0]=0.f; rsl[0][1]=0.f; rsl[1][0]=0.f; rsl[1][1]=0.f;

    #pragma unroll 1
    for (int kb = 0; kb < 8; kb++){
        int kt = kb*4 + (wc >> 1);
        int nb = (wc & 1) * 4;

        float C[2][4][4];
        #pragma unroll
        for (int a=0;a<2;a++)
            #pragma unroll
            for (int bb=0;bb<4;bb++)
                #pragma unroll
                for (int c=0;c<4;c++) C[a][bb][c]=0.f;

        #pragma unroll 1
        for (int ft = 0; ft < 8; ft++){
            const unsigned* As = smQ + ft*1024;
            const unsigned* Bb = g_Kpb + ((size_t)((b*32 + kt)*8 + ft))*2048;
            #pragma unroll
            for (int ks = 0; ks < 4; ks++){
                uint4 Af[2];
                #pragma unroll
                for (int mf=0; mf<2; mf++)
                    Af[mf] = *(const uint4*)(As + ((ks*2 + mf)*32 + lane)*4);
                uint2 Bf[4];
                #pragma unroll
                for (int nf=0; nf<4; nf++)
                    Bf[nf] = *(const uint2*)(Bb + ((ks*8 + nb + nf)*32 + lane)*2);
                #pragma unroll
                for (int mf=0; mf<2; mf++)
                    #pragma unroll
                    for (int nf=0; nf<4; nf++)
                        mma_bf16(C[mf][nf], (const unsigned*)&Af[mf], (const unsigned*)&Bf[nf]);
            }
        }

        #pragma unroll
        for (int mf = 0; mf < 2; mf++)
            #pragma unroll
            for (int rh = 0; rh < 2; rh++){
                int row = qt*32 + mf*16 + g + 8*rh;
                float rs = 0.f;
                #pragma unroll
                for (int nf = 0; nf < 4; nf++){
                    float e0 = fexp(C[mf][nf][rh*2+0] * SCALE);
                    float e1 = fexp(C[mf][nf][rh*2+1] * SCALE);
                    rs += e0 + e1;
                    int kcol = kb*256 + wc*32 + nf*8 + 2*t;
                    size_t idx = ((size_t)(b*QQ + row))*KK2 + kcol;
                    ((__nv_bfloat162*)g_E)[idx >> 1] = __floats2bfloat162_rn(e0, e1);
                }
                rsl[mf][rh] += rs;
            }
    }

    #pragma unroll
    for (int mf = 0; mf < 2; mf++)
        #pragma unroll
        for (int rh = 0; rh < 2; rh++){
            float rs = rsl[mf][rh];
            rs += __shfl_xor_sync(0xffffffffu, rs, 1);
            rs += __shfl_xor_sync(0xffffffffu, rs, 2);
            if (t == 0) l_s[wc*32 + mf*16 + g + 8*rh] = rs;
        }
    __syncthreads();
    if (tid < 32){
        float s = 0.f;
        #pragma unroll
        for (int w = 0; w < 8; w++) s += l_s[w*32 + tid];
        g_linv[b*QQ + qt*32 + tid] = 1.0f / s;
    }
}

// ---------------- pass2 (fused, fp16 mma, packed masks, 2 CTAs/SM): W in smem; O = W*V ----------------
#define WROW 36   // W row stride in 32-bit words
__global__ void __launch_bounds__(NTHREADS, 2) pass2_kernel(
    float* __restrict__ out,
    const float* __restrict__ cq, const float* __restrict__ ck,
    const float* __restrict__ bias)
{
    extern __shared__ unsigned smw[];   // 2 * 32*36 words = 9216 B
    int tid = threadIdx.x, lane = tid & 31, wc = tid >> 5;
    int g = lane >> 2, t = lane & 3;
    int b = blockIdx.x >> 6, qt = blockIdx.x & 63;
    const int q0 = qt*32;

    // build role: thread owns row brow (0..31), 8 cols at bc0 (within 64-col k-tile)
    const int brow = tid >> 3;
    const int s8   = tid & 7;
    const int bc0  = s8 * 8;
    const float2 cqv = *(const float2*)(cq + ((size_t)(b*QQ + q0 + brow))*2);
    const float li   = g_linv[b*QQ + q0 + brow];
    const size_t erow = ((size_t)(b*QQ + q0 + brow))*KK2;
    const unsigned* pam_row = g_pam + ((size_t)(b*QQ + q0 + brow))*64;
    const unsigned* pal_row = g_pal + ((size_t)(b*QQ + q0 + brow))*64;
    const float bsc = __ldg(bias);

    float C[2][8][4];
    #pragma unroll
    for (int a=0;a<2;a++)
        #pragma unroll
        for (int n=0;n<8;n++)
            #pragma unroll
            for (int c=0;c<4;c++) C[a][n][c]=0.f;

    #pragma unroll 1
    for (int kt = 0; kt < 32; kt++){
        unsigned* Wb = smw + (kt & 1) * (32*WROW);

        // ---- build W tile (32x64 fp16): 8 elems per thread ----
        {
            int cb = kt*64 + bc0;
            uint4 eu = *(const uint4*)(g_E + erow + cb);       // 8 bf16
            const unsigned* ew = (const unsigned*)&eu;
            unsigned am8 = (pam_row[cb>>5] >> (cb&31)) & 0xFFu;
            unsigned al8 = (pal_row[cb>>5] >> (cb&31)) & 0xFFu;
            float4 ck4[4];
            #pragma unroll
            for (int i = 0; i < 4; i++)
                ck4[i] = __ldg((const float4*)(ck + ((size_t)(b*KK2 + cb))*2) + i);
            const float2* ckp = (const float2*)&ck4[0];

            float wv[8];
            #pragma unroll
            for (int c = 0; c < 8; c++){
                __nv_bfloat162 e2 = *(__nv_bfloat162*)&ew[c>>1];
                float e = __bfloat162float((c & 1) ? e2.y : e2.x) * li;
                float dx = cqv.x - ckp[c].x;
                float dy = cqv.y - ckp[c].y;
                float r2 = fmaxf(dx*dx + dy*dy, 1e-30f);
                float d  = ((al8 >> c) & 1u) ? 0.f : (r2 * frsqrt2(r2) * bsc);
                wv[c] = ((am8 >> c) & 1u) ? 0.f : (e - d);
            }
            __half2 h0 = __floats2half2_rn(wv[0], wv[1]);
            __half2 h1 = __floats2half2_rn(wv[2], wv[3]);
            __half2 h2 = __floats2half2_rn(wv[4], wv[5]);
            __half2 h3 = __floats2half2_rn(wv[6], wv[7]);
            *(uint4*)(Wb + brow*WROW + s8*4) =
                make_uint4(*(unsigned*)&h0, *(unsigned*)&h1, *(unsigned*)&h2, *(unsigned*)&h3);
        }
        __syncthreads();

        // ---- mma fp16: A frags from Wb (4x LDS.32, conflict-free), B from g_Vph ----
        const unsigned* Bb = g_Vph + ((size_t)((b*8 + wc)*32 + kt))*2048;
        #pragma unroll
        for (int ks = 0; ks < 4; ks++){
            unsigned Af[2][4];
            #pragma unroll
            for (int mf = 0; mf < 2; mf++){
                int rowbase = (mf*16 + g)*WROW + ks*8 + t;
                Af[mf][0] = Wb[rowbase];
                Af[mf][1] = Wb[rowbase + 8*WROW];
                Af[mf][2] = Wb[rowbase + 4];
                Af[mf][3] = Wb[rowbase + 8*WROW + 4];
            }
            uint2 Bf[8];
            #pragma unroll
            for (int nf = 0; nf < 8; nf++)
                Bf[nf] = *(const uint2*)(Bb + ((ks*8 + nf)*32 + lane)*2);
            #pragma unroll
            for (int mf = 0; mf < 2; mf++)
                #pragma unroll
                for (int nf = 0; nf < 8; nf++)
                    mma_fp16(C[mf][nf], Af[mf], (const unsigned*)&Bf[nf]);
        }
        // next build writes the other buffer; sync(kt+1) transitively orders
        // mma(kt) readers before build(kt+2) rewrites this buffer.
    }

    // ---- epilogue ----
    #pragma unroll
    for (int mf = 0; mf < 2; mf++)
        #pragma unroll
        for (int rh = 0; rh < 2; rh++){
            int row = q0 + mf*16 + g + 8*rh;
            float* orow = out + ((size_t)(b*QQ + row))*FVV;
            #pragma unroll
            for (int nf = 0; nf < 8; nf++){
                int fv = wc*64 + nf*8 + 2*t;
                *(float2*)(orow + fv) = make_float2(C[mf][nf][rh*2+0], C[mf][nf][rh*2+1]);
            }
        }
}

extern "C" void kernel_launch(void* const* d_in, const int* in_sizes, int n_in,
                              void* d_out, int out_size)
{
    const float*         q    = (const float*)d_in[0];
    const float*         k    = (const float*)d_in[1];
    const float*         v    = (const float*)d_in[2];
    const float*         cq   = (const float*)d_in[3];
    const float*         ck   = (const float*)d_in[4];
    const unsigned char* am   = (const unsigned char*)d_in[5];
    const unsigned char* al   = (const unsigned char*)d_in[6];
    const float*         bias = (const float*)d_in[7];
    float*               out  = (float*)d_out;

    static int smem_set = 0;
    if (!smem_set){
        cudaFuncSetAttribute(pass1_kernel, cudaFuncAttributeMaxDynamicSharedMemorySize, 33792);
        cudaFuncSetAttribute(pass2_kernel, cudaFuncAttributeMaxDynamicSharedMemorySize, 9216);
        smem_set = 1;
    }

    detect_mask_kernel<<<1, 1>>>(am);
    prep_qb_kernel<<<4096, NTHREADS>>>(q);
    prep_kb_kernel<<<8192, NTHREADS>>>(k);
    prep_vh_kernel<<<2048, NTHREADS>>>(v);
    pass1_kernel<<<512, NTHREADS, 33792>>>(am, al);
    pass2_kernel<<<512, NTHREADS, 9216>>>(out, cq, ck, bias);
}

// round 15
// speedup vs baseline: 1.1267x; 1.1267x over previous
#include <cuda_runtime.h>
#include <cuda_bf16.h>
#include <cuda_fp16.h>
#include <math.h>

#define BB   8
#define QQ   2048
#define KK2  2048
#define FF   512
#define FVV  512
#define NTHREADS 256

// ---------------- scratch (device globals; no runtime allocation) ----------------
// bf16 A-blob (64x64): [ks4][mf4][lane32][4 b32]
// bf16/fp16 B-blob (64k x 64n): [ks4][nf8][lane32][2 b32]
__device__ __align__(16) unsigned g_Qpb[4194304];     // (b, qt32, ft8) bf16 A-blobs   16.8MB
__device__ __align__(16) unsigned g_Kpb[4194304];     // (b, kt32, ft8) bf16 B-blobs   16.8MB
__device__ __align__(16) unsigned g_Vph[4194304];     // (b, fvt8, kt32) fp16 B-blobs  16.8MB
__device__ __align__(16) __nv_bfloat16 g_E[33554432]; // exp(logits) row-major         67MB
__device__ int g_mask_is_int32;

// ---------------- helpers ----------------
__device__ __forceinline__ void mma_bf16(float c[4], const unsigned* a, const unsigned* b){
    asm volatile("mma.sync.aligned.m16n8k16.row.col.f32.bf16.bf16.f32 "
        "{%0,%1,%2,%3}, {%4,%5,%6,%7}, {%8,%9}, {%0,%1,%2,%3};"
        : "+f"(c[0]), "+f"(c[1]), "+f"(c[2]), "+f"(c[3])
        : "r"(a[0]), "r"(a[1]), "r"(a[2]), "r"(a[3]), "r"(b[0]), "r"(b[1]));
}
__device__ __forceinline__ void mma_fp16(float c[4], const unsigned* a, const unsigned* b){
    asm volatile("mma.sync.aligned.m16n8k16.row.col.f32.f16.f16.f32 "
        "{%0,%1,%2,%3}, {%4,%5,%6,%7}, {%8,%9}, {%0,%1,%2,%3};"
        : "+f"(c[0]), "+f"(c[1]), "+f"(c[2]), "+f"(c[3])
        : "r"(a[0]), "r"(a[1]), "r"(a[2]), "r"(a[3]), "r"(b[0]), "r"(b[1]));
}
// exp on the FMA pipe: 2^(x*log2e), deg-5 poly (rel err ~2e-7 for |x| < 15)
__device__ __forceinline__ float fexp(float x){
    float t = x * 1.4426950408889634f;
    float r = rintf(t);
    float f = t - r;
    float p = 1.3333558146428443e-3f;
    p = fmaf(p, f, 9.618129107628477e-3f);
    p = fmaf(p, f, 5.550410866482158e-2f);
    p = fmaf(p, f, 2.402265069591007e-1f);
    p = fmaf(p, f, 6.931471805599453e-1f);
    p = fmaf(p, f, 1.0f);
    return __int_as_float(((int)r + 127) << 23) * p;
}
// rsqrt on FMA pipe, 2 Newton steps (~1e-6 rel)
__device__ __forceinline__ float frsqrt2(float x){
    float y = __int_as_float(0x5f3759df - (__float_as_int(x) >> 1));
    y = y * (1.5f - 0.5f * x * y * y);
    y = y * (1.5f - 0.5f * x * y * y);
    return y;
}

// ---------------- mask dtype probe ----------------
__global__ void detect_mask_kernel(const unsigned char* am){
    unsigned nz = 0;
    #pragma unroll 8
    for (int i = 0; i < 1024; i++) nz |= am[4*i+1] | am[4*i+2] | am[4*i+3];
    g_mask_is_int32 = (nz == 0u) ? 1 : 0;
}

// ---------------- prep Q -> bf16 A-fragment blobs ----------------
__global__ void __launch_bounds__(NTHREADS) prep_qb_kernel(const float* __restrict__ q){
    int w = blockIdx.x * 8 + (threadIdx.x >> 5);
    int lane = threadIdx.x & 31, g = lane >> 2, t = lane & 3;
    int mf = w & 3, ks = (w>>2)&3, ft = (w>>4)&7, qt = (w>>7)&31, b = w>>12;
    unsigned rr[4];
    #pragma unroll
    for (int rh = 0; rh < 2; rh++){
        int row = qt*64 + mf*16 + g + 8*rh;
        const float* qp = q + ((size_t)(b*QQ + row))*FF + ft*64 + ks*16 + 2*t;
        float2 x0 = *(const float2*)qp;
        float2 x1 = *(const float2*)(qp + 8);
        __nv_bfloat162 h0 = __floats2bfloat162_rn(x0.x, x0.y);
        __nv_bfloat162 h1 = __floats2bfloat162_rn(x1.x, x1.y);
        rr[rh]   = *(unsigned*)&h0;
        rr[rh+2] = *(unsigned*)&h1;
    }
    size_t blob = ((size_t)((b*32 + qt)*8 + ft))*2048;
    *(uint4*)(g_Qpb + blob + ((ks*4 + mf)*32 + lane)*4) = make_uint4(rr[0],rr[1],rr[2],rr[3]);
}

// ---------------- prep K -> bf16 B-fragment blobs ----------------
__global__ void __launch_bounds__(NTHREADS) prep_kb_kernel(const float* __restrict__ k){
    int w = blockIdx.x * 8 + (threadIdx.x >> 5);
    int lane = threadIdx.x & 31, g = lane >> 2, t = lane & 3;
    int nf = w & 7, ks = (w>>3)&3, ft = (w>>5)&7, kt = (w>>8)&31, b = w>>13;
    int n = kt*64 + nf*8 + g;
    const float* kp = k + ((size_t)(b*KK2 + n))*FF + ft*64 + ks*16 + 2*t;
    float2 x0 = *(const float2*)kp;
    float2 x1 = *(const float2*)(kp + 8);
    __nv_bfloat162 h0 = __floats2bfloat162_rn(x0.x, x0.y);
    __nv_bfloat162 h1 = __floats2bfloat162_rn(x1.x, x1.y);
    size_t blob = ((size_t)((b*32 + kt)*8 + ft))*2048;
    *(uint2*)(g_Kpb + blob + ((ks*8 + nf)*32 + lane)*2) =
        make_uint2(*(unsigned*)&h0, *(unsigned*)&h1);
}

// ---------------- prep V -> fp16 B-fragment blobs (smem transpose, coalesced) ----------------
__global__ void __launch_bounds__(NTHREADS) prep_vh_kernel(const float* __restrict__ v){
    __shared__ float ts[64][68];
    int bx = blockIdx.x;                 // 8 fb x 32 kt x 8 b
    int fb = bx & 7, kt = (bx>>3) & 31, b = bx >> 8;
    int tid = threadIdx.x;
    {
        int fc = (tid & 15) * 4;
        int k0 = tid >> 4;
        #pragma unroll
        for (int it = 0; it < 4; it++){
            int kk = it*16 + k0;
            float4 x = *(const float4*)(v + ((size_t)(b*KK2 + kt*64 + kk))*FVV + fb*64 + fc);
            *(float4*)&ts[kk][fc] = x;
        }
    }
    __syncthreads();
    int lane = tid & 31, g = lane >> 2, t = lane & 3;
    int nf = tid >> 5;
    int n = nf*8 + g;
    unsigned* dst = g_Vph + ((size_t)((b*8 + fb)*32 + kt))*2048;
    #pragma unroll
    for (int ks = 0; ks < 4; ks++){
        __half2 w0 = __floats2half2_rn(ts[ks*16 + 2*t    ][n], ts[ks*16 + 2*t + 1][n]);
        __half2 w1 = __floats2half2_rn(ts[ks*16 + 2*t + 8][n], ts[ks*16 + 2*t + 9][n]);
        *(uint2*)(dst + ((ks*8 + nf)*32 + lane)*2) =
            make_uint2(*(unsigned*)&w0, *(unsigned*)&w1);
    }
}

// ---------------- fused attention kernel: phase A (S,E,l) + phase B (W*V) ----------------
// CTA = (b, 32-row q-tile), 2 CTAs/SM. Phase A writes E rows (L2-hot for phase B),
// keeps 1/l in smem. Phase B = R12 pass2 body, reading the CTA's own E rows.
// smem: [0..32KB) smQ (A) / W double-buffer (B, 9216B); [32KB..+1KB) l_s; then lin_s[32].
#define WROW 36   // W row stride in 32-bit words
__global__ void __launch_bounds__(NTHREADS, 2) fused_kernel(
    float* __restrict__ out,
    const float* __restrict__ cq, const float* __restrict__ ck,
    const unsigned char* __restrict__ am, const unsigned char* __restrict__ al,
    const float* __restrict__ bias)
{
    extern __shared__ unsigned smem_u[];
    unsigned* smQ  = smem_u;                       // phase A: 8192 words (32KB)
    unsigned* smw  = smem_u;                       // phase B: W double buffer (2304 words)
    float* l_s   = (float*)(smem_u + 8192);        // 8 warps * 32 rows
    float* lin_s = (float*)(smem_u + 8192 + 256);  // 32 floats

    int tid = threadIdx.x, lane = tid & 31, wc = tid >> 5;
    int g = lane >> 2, t = lane & 3;
    int b = blockIdx.x >> 6, qt = blockIdx.x & 63;
    const int q0 = qt*32;
    const float SCALE = 0.044194173824159216f;  // 1/sqrt(512)

    // ================= phase A: S = QK^T * scale; E = exp(S); l =================
    {
        const int qt64 = qt >> 1, mb = (qt & 1) * 2;
        const unsigned* base = g_Qpb + ((size_t)((b*32 + qt64)*8))*2048;
        #pragma unroll
        for (int i = 0; i < 8; i++){
            int j = tid + 256*i;
            int lj = j & 31, mf = (j>>5)&1, ks = (j>>6)&3, ft = j>>8;
            *(uint4*)(smQ + ((size_t)j)*4) =
                *(const uint4*)(base + ft*2048 + ((ks*4 + mb + mf)*32 + lj)*4);
        }
    }
    __syncthreads();

    {
        float rsl[2][2];
        rsl[0][0]=0.f; rsl[0][1]=0.f; rsl[1][0]=0.f; rsl[1][1]=0.f;

        #pragma unroll 1
        for (int kb = 0; kb < 8; kb++){
            int kt = kb*4 + (wc >> 1);
            int nb = (wc & 1) * 4;

            float C[2][4][4];
            #pragma unroll
            for (int a=0;a<2;a++)
                #pragma unroll
                for (int bb=0;bb<4;bb++)
                    #pragma unroll
                    for (int c=0;c<4;c++) C[a][bb][c]=0.f;

            #pragma unroll 1
            for (int ft = 0; ft < 8; ft++){
                const unsigned* As = smQ + ft*1024;
                const unsigned* Bb = g_Kpb + ((size_t)((b*32 + kt)*8 + ft))*2048;
                #pragma unroll
                for (int ks = 0; ks < 4; ks++){
                    uint4 Af[2];
                    #pragma unroll
                    for (int mf=0; mf<2; mf++)
                        Af[mf] = *(const uint4*)(As + ((ks*2 + mf)*32 + lane)*4);
                    uint2 Bf[4];
                    #pragma unroll
                    for (int nf=0; nf<4; nf++)
                        Bf[nf] = *(const uint2*)(Bb + ((ks*8 + nb + nf)*32 + lane)*2);
                    #pragma unroll
                    for (int mf=0; mf<2; mf++)
                        #pragma unroll
                        for (int nf=0; nf<4; nf++)
                            mma_bf16(C[mf][nf], (const unsigned*)&Af[mf], (const unsigned*)&Bf[nf]);
                }
            }

            #pragma unroll
            for (int mf = 0; mf < 2; mf++)
                #pragma unroll
                for (int rh = 0; rh < 2; rh++){
                    int row = q0 + mf*16 + g + 8*rh;
                    float rs = 0.f;
                    #pragma unroll
                    for (int nf = 0; nf < 4; nf++){
                        float e0 = fexp(C[mf][nf][rh*2+0] * SCALE);
                        float e1 = fexp(C[mf][nf][rh*2+1] * SCALE);
                        rs += e0 + e1;
                        int kcol = kb*256 + wc*32 + nf*8 + 2*t;
                        size_t idx = ((size_t)(b*QQ + row))*KK2 + kcol;
                        ((__nv_bfloat162*)g_E)[idx >> 1] = __floats2bfloat162_rn(e0, e1);
                    }
                    rsl[mf][rh] += rs;
                }
        }

        #pragma unroll
        for (int mf = 0; mf < 2; mf++)
            #pragma unroll
            for (int rh = 0; rh < 2; rh++){
                float rs = rsl[mf][rh];
                rs += __shfl_xor_sync(0xffffffffu, rs, 1);
                rs += __shfl_xor_sync(0xffffffffu, rs, 2);
                if (t == 0) l_s[wc*32 + mf*16 + g + 8*rh] = rs;
            }
        __syncthreads();
        if (tid < 32){
            float s = 0.f;
            #pragma unroll
            for (int w = 0; w < 8; w++) s += l_s[w*32 + tid];
            lin_s[tid] = 1.0f / s;
        }
        __syncthreads();
    }

    // ================= phase B: W = attn?0:(E/l - alibi?0:dist*bias); O = W*V =================
    const int brow = tid >> 3;
    const int s8   = tid & 7;
    const int bc0  = s8 * 8;
    const float2 cqv = *(const float2*)(cq + ((size_t)(b*QQ + q0 + brow))*2);
    const float li   = lin_s[brow];
    const size_t erow = ((size_t)(b*QQ + q0 + brow))*KK2;
    const float bsc = __ldg(bias);
    const int m32 = g_mask_is_int32;

    float C[2][8][4];
    #pragma unroll
    for (int a=0;a<2;a++)
        #pragma unroll
        for (int n=0;n<8;n++)
            #pragma unroll
            for (int c=0;c<4;c++) C[a][n][c]=0.f;

    #pragma unroll 1
    for (int kt = 0; kt < 32; kt++){
        unsigned* Wb = smw + (kt & 1) * (32*WROW);

        // ---- build W tile (32x64 fp16): 8 elems per thread ----
        {
            int cb = kt*64 + bc0;
            uint4 eu = *(const uint4*)(g_E + erow + cb);       // 8 bf16 (L2-hot)
            const unsigned* ew = (const unsigned*)&eu;
            int amv[8], alv[8];
            if (m32){
                const int4* ap = (const int4*)((const int*)am + erow + cb);
                const int4* lp = (const int4*)((const int*)al + erow + cb);
                int4 a0 = ap[0], a1 = ap[1], l0 = lp[0], l1 = lp[1];
                amv[0]=a0.x; amv[1]=a0.y; amv[2]=a0.z; amv[3]=a0.w;
                amv[4]=a1.x; amv[5]=a1.y; amv[6]=a1.z; amv[7]=a1.w;
                alv[0]=l0.x; alv[1]=l0.y; alv[2]=l0.z; alv[3]=l0.w;
                alv[4]=l1.x; alv[5]=l1.y; alv[6]=l1.z; alv[7]=l1.w;
            } else {
                uint2 au = *(const uint2*)(am + erow + cb);
                uint2 lu = *(const uint2*)(al + erow + cb);
                const unsigned char* ab = (const unsigned char*)&au;
                const unsigned char* lb = (const unsigned char*)&lu;
                #pragma unroll
                for (int c = 0; c < 8; c++){ amv[c] = ab[c]; alv[c] = lb[c]; }
            }
            float4 ck4[4];
            #pragma unroll
            for (int i = 0; i < 4; i++)
                ck4[i] = __ldg((const float4*)(ck + ((size_t)(b*KK2 + cb))*2) + i);
            const float2* ckp = (const float2*)&ck4[0];

            float wv[8];
            #pragma unroll
            for (int c = 0; c < 8; c++){
                __nv_bfloat162 e2 = *(__nv_bfloat162*)&ew[c>>1];
                float e = __bfloat162float((c & 1) ? e2.y : e2.x) * li;
                float dx = cqv.x - ckp[c].x;
                float dy = cqv.y - ckp[c].y;
                float r2 = fmaxf(dx*dx + dy*dy, 1e-30f);
                float d  = alv[c] ? 0.f : (r2 * frsqrt2(r2) * bsc);
                wv[c] = amv[c] ? 0.f : (e - d);
            }
            __half2 h0 = __floats2half2_rn(wv[0], wv[1]);
            __half2 h1 = __floats2half2_rn(wv[2], wv[3]);
            __half2 h2 = __floats2half2_rn(wv[4], wv[5]);
            __half2 h3 = __floats2half2_rn(wv[6], wv[7]);
            *(uint4*)(Wb + brow*WROW + s8*4) =
                make_uint4(*(unsigned*)&h0, *(unsigned*)&h1, *(unsigned*)&h2, *(unsigned*)&h3);
        }
        __syncthreads();

        // ---- mma fp16: A frags from Wb (4x LDS.32, conflict-free), B from g_Vph ----
        const unsigned* Bb = g_Vph + ((size_t)((b*8 + wc)*32 + kt))*2048;
        #pragma unroll
        for (int ks = 0; ks < 4; ks++){
            unsigned Af[2][4];
            #pragma unroll
            for (int mf = 0; mf < 2; mf++){
                int rowbase = (mf*16 + g)*WROW + ks*8 + t;
                Af[mf][0] = Wb[rowbase];
                Af[mf][1] = Wb[rowbase + 8*WROW];
                Af[mf][2] = Wb[rowbase + 4];
                Af[mf][3] = Wb[rowbase + 8*WROW + 4];
            }
            uint2 Bf[8];
            #pragma unroll
            for (int nf = 0; nf < 8; nf++)
                Bf[nf] = *(const uint2*)(Bb + ((ks*8 + nf)*32 + lane)*2);
            #pragma unroll
            for (int mf = 0; mf < 2; mf++)
                #pragma unroll
                for (int nf = 0; nf < 8; nf++)
                    mma_fp16(C[mf][nf], Af[mf], (const unsigned*)&Bf[nf]);
        }
        // next build writes the other buffer; sync(kt+1) transitively orders
        // mma(kt) readers before build(kt+2) rewrites this buffer.
    }

    // ---- epilogue ----
    #pragma unroll
    for (int mf = 0; mf < 2; mf++)
        #pragma unroll
        for (int rh = 0; rh < 2; rh++){
            int row = q0 + mf*16 + g + 8*rh;
            float* orow = out + ((size_t)(b*QQ + row))*FVV;
            #pragma unroll
            for (int nf = 0; nf < 8; nf++){
                int fv = wc*64 + nf*8 + 2*t;
                *(float2*)(orow + fv) = make_float2(C[mf][nf][rh*2+0], C[mf][nf][rh*2+1]);
            }
        }
}

extern "C" void kernel_launch(void* const* d_in, const int* in_sizes, int n_in,
                              void* d_out, int out_size)
{
    const float*         q    = (const float*)d_in[0];
    const float*         k    = (const float*)d_in[1];
    const float*         v    = (const float*)d_in[2];
    const float*         cq   = (const float*)d_in[3];
    const float*         ck   = (const float*)d_in[4];
    const unsigned char* am   = (const unsigned char*)d_in[5];
    const unsigned char* al   = (const unsigned char*)d_in[6];
    const float*         bias = (const float*)d_in[7];
    float*               out  = (float*)d_out;

    static int smem_set = 0;
    if (!smem_set){
        cudaFuncSetAttribute(fused_kernel, cudaFuncAttributeMaxDynamicSharedMemorySize, 33920);
        smem_set = 1;
    }

    detect_mask_kernel<<<1, 1>>>(am);
    prep_qb_kernel<<<4096, NTHREADS>>>(q);
    prep_kb_kernel<<<8192, NTHREADS>>>(k);
    prep_vh_kernel<<<2048, NTHREADS>>>(v);
    fused_kernel<<<512, NTHREADS, 33920>>>(out, cq, ck, am, al, bias);
}

// round 16
// speedup vs baseline: 1.2808x; 1.1368x over previous
#include <cuda_runtime.h>
#include <cuda_bf16.h>
#include <cuda_fp16.h>
#include <math.h>

#define BB   8
#define QQ   2048
#define KK2  2048
#define FF   512
#define FVV  512
#define NTHREADS 256

// ---------------- scratch (device globals; no runtime allocation) ----------------
// bf16 A-blob (64x64): [ks4][mf4][lane32][4 b32]
// bf16/fp16 B-blob (64k x 64n): [ks4][nf8][lane32][2 b32]
__device__ __align__(16) unsigned g_Qpb[4194304];     // (b, qt32, ft8) bf16 A-blobs   16.8MB
__device__ __align__(16) unsigned g_Kpb[4194304];     // (b, kt32, ft8) bf16 B-blobs   16.8MB
__device__ __align__(16) unsigned g_Vph[4194304];     // (b, fvt8, kt32) fp16 B-blobs  16.8MB
__device__ __align__(16) __nv_bfloat16 g_E[33554432]; // exp(logits) row-major         67MB
__device__ float g_linv[BB*QQ];
__device__ int   g_mask_is_int32;

// ---------------- helpers ----------------
__device__ __forceinline__ void mma_bf16(float c[4], const unsigned* a, const unsigned* b){
    asm volatile("mma.sync.aligned.m16n8k16.row.col.f32.bf16.bf16.f32 "
        "{%0,%1,%2,%3}, {%4,%5,%6,%7}, {%8,%9}, {%0,%1,%2,%3};"
        : "+f"(c[0]), "+f"(c[1]), "+f"(c[2]), "+f"(c[3])
        : "r"(a[0]), "r"(a[1]), "r"(a[2]), "r"(a[3]), "r"(b[0]), "r"(b[1]));
}
__device__ __forceinline__ void mma_fp16(float c[4], const unsigned* a, const unsigned* b){
    asm volatile("mma.sync.aligned.m16n8k16.row.col.f32.f16.f16.f32 "
        "{%0,%1,%2,%3}, {%4,%5,%6,%7}, {%8,%9}, {%0,%1,%2,%3};"
        : "+f"(c[0]), "+f"(c[1]), "+f"(c[2]), "+f"(c[3])
        : "r"(a[0]), "r"(a[1]), "r"(a[2]), "r"(a[3]), "r"(b[0]), "r"(b[1]));
}
// exp on the FMA pipe: 2^(x*log2e), deg-5 poly (rel err ~2e-7 for |x| < 15)
__device__ __forceinline__ float fexp(float x){
    float t = x * 1.4426950408889634f;
    float r = rintf(t);
    float f = t - r;
    float p = 1.3333558146428443e-3f;
    p = fmaf(p, f, 9.618129107628477e-3f);
    p = fmaf(p, f, 5.550410866482158e-2f);
    p = fmaf(p, f, 2.402265069591007e-1f);
    p = fmaf(p, f, 6.931471805599453e-1f);
    p = fmaf(p, f, 1.0f);
    return __int_as_float(((int)r + 127) << 23) * p;
}
// rsqrt on FMA pipe, 2 Newton steps (~1e-6 rel)
__device__ __forceinline__ float frsqrt2(float x){
    float y = __int_as_float(0x5f3759df - (__float_as_int(x) >> 1));
    y = y * (1.5f - 0.5f * x * y * y);
    y = y * (1.5f - 0.5f * x * y * y);
    return y;
}

// ---------------- mask dtype probe (parallel: 256 threads, ~2us) ----------------
__global__ void detect_mask_kernel(const unsigned char* am){
    int tid = threadIdx.x;
    unsigned nz = 0;
    #pragma unroll
    for (int i = 0; i < 16; i++){
        int e = tid + 256*i;                   // sample elements 0..4095
        nz |= am[4*e+1] | am[4*e+2] | am[4*e+3];
    }
    int any = __syncthreads_or((int)nz);
    if (tid == 0) g_mask_is_int32 = any ? 0 : 1;
}

// ---------------- merged prep: Q -> bf16 A-blobs; K -> bf16 B-blobs; V -> fp16 B-blobs ----------------
// grid = 4096 (Q) + 8192 (K) + 2048 (V) = 14336
__global__ void __launch_bounds__(NTHREADS) prep_all_kernel(
    const float* __restrict__ q, const float* __restrict__ k, const float* __restrict__ v)
{
    int bx = blockIdx.x;
    int tid = threadIdx.x;
    int lane = tid & 31, g = lane >> 2, t = lane & 3;

    if (bx < 4096){
        // ---- Q prep ----
        int w = bx * 8 + (tid >> 5);
        int mf = w & 3, ks = (w>>2)&3, ft = (w>>4)&7, qt = (w>>7)&31, b = w>>12;
        unsigned rr[4];
        #pragma unroll
        for (int rh = 0; rh < 2; rh++){
            int row = qt*64 + mf*16 + g + 8*rh;
            const float* qp = q + ((size_t)(b*QQ + row))*FF + ft*64 + ks*16 + 2*t;
            float2 x0 = *(const float2*)qp;
            float2 x1 = *(const float2*)(qp + 8);
            __nv_bfloat162 h0 = __floats2bfloat162_rn(x0.x, x0.y);
            __nv_bfloat162 h1 = __floats2bfloat162_rn(x1.x, x1.y);
            rr[rh]   = *(unsigned*)&h0;
            rr[rh+2] = *(unsigned*)&h1;
        }
        size_t blob = ((size_t)((b*32 + qt)*8 + ft))*2048;
        *(uint4*)(g_Qpb + blob + ((ks*4 + mf)*32 + lane)*4) = make_uint4(rr[0],rr[1],rr[2],rr[3]);
    } else if (bx < 12288){
        // ---- K prep ----
        int w = (bx - 4096) * 8 + (tid >> 5);
        int nf = w & 7, ks = (w>>3)&3, ft = (w>>5)&7, kt = (w>>8)&31, b = w>>13;
        int n = kt*64 + nf*8 + g;
        const float* kp = k + ((size_t)(b*KK2 + n))*FF + ft*64 + ks*16 + 2*t;
        float2 x0 = *(const float2*)kp;
        float2 x1 = *(const float2*)(kp + 8);
        __nv_bfloat162 h0 = __floats2bfloat162_rn(x0.x, x0.y);
        __nv_bfloat162 h1 = __floats2bfloat162_rn(x1.x, x1.y);
        size_t blob = ((size_t)((b*32 + kt)*8 + ft))*2048;
        *(uint2*)(g_Kpb + blob + ((ks*8 + nf)*32 + lane)*2) =
            make_uint2(*(unsigned*)&h0, *(unsigned*)&h1);
    } else {
        // ---- V prep (smem transpose) ----
        __shared__ float ts[64][68];
        int vx = bx - 12288;                 // 8 fb x 32 kt x 8 b
        int fb = vx & 7, kt = (vx>>3) & 31, b = vx >> 8;
        {
            int fc = (tid & 15) * 4;
            int k0 = tid >> 4;
            #pragma unroll
            for (int it = 0; it < 4; it++){
                int kk = it*16 + k0;
                float4 x = *(const float4*)(v + ((size_t)(b*KK2 + kt*64 + kk))*FVV + fb*64 + fc);
                *(float4*)&ts[kk][fc] = x;
            }
        }
        __syncthreads();
        int nf = tid >> 5;
        int n = nf*8 + g;
        unsigned* dst = g_Vph + ((size_t)((b*8 + fb)*32 + kt))*2048;
        #pragma unroll
        for (int ks = 0; ks < 4; ks++){
            __half2 w0 = __floats2half2_rn(ts[ks*16 + 2*t    ][n], ts[ks*16 + 2*t + 1][n]);
            __half2 w1 = __floats2half2_rn(ts[ks*16 + 2*t + 8][n], ts[ks*16 + 2*t + 9][n]);
            *(uint2*)(dst + ((ks*8 + nf)*32 + lane)*2) =
                make_uint2(*(unsigned*)&w0, *(unsigned*)&w1);
        }
    }
}

// ---------------- pass1 (32-row q-tiles, 2 CTAs/SM): S=QK^T*scale; E=exp(S); linv ----------------
__global__ void __launch_bounds__(NTHREADS, 2) pass1_kernel(void){
    extern __shared__ unsigned smem_u[];
    unsigned* smQ = smem_u;                    // 8192 words = 32KB
    float* l_s = (float*)(smem_u + 8192);      // 8 warps * 32 rows

    int tid = threadIdx.x, lane = tid & 31, wc = tid >> 5;
    int g = lane >> 2, t = lane & 3;
    int b = blockIdx.x >> 6, qt = blockIdx.x & 63;
    const int qt64 = qt >> 1, mb = (qt & 1) * 2;
    const float SCALE = 0.044194173824159216f;  // 1/sqrt(512)

    {
        const unsigned* base = g_Qpb + ((size_t)((b*32 + qt64)*8))*2048;
        #pragma unroll
        for (int i = 0; i < 8; i++){
            int j = tid + 256*i;
            int lj = j & 31, mf = (j>>5)&1, ks = (j>>6)&3, ft = j>>8;
            *(uint4*)(smQ + ((size_t)j)*4) =
                *(const uint4*)(base + ft*2048 + ((ks*4 + mb + mf)*32 + lj)*4);
        }
    }
    __syncthreads();

    float rsl[2][2];
    rsl[0][0]=0.f; rsl[0][1]=0.f; rsl[1][0]=0.f; rsl[1][1]=0.f;

    #pragma unroll 1
    for (int kb = 0; kb < 8; kb++){
        int kt = kb*4 + (wc >> 1);
        int nb = (wc & 1) * 4;

        float C[2][4][4];
        #pragma unroll
        for (int a=0;a<2;a++)
            #pragma unroll
            for (int bb=0;bb<4;bb++)
                #pragma unroll
                for (int c=0;c<4;c++) C[a][bb][c]=0.f;

        #pragma unroll 1
        for (int ft = 0; ft < 8; ft++){
            const unsigned* As = smQ + ft*1024;
            const unsigned* Bb = g_Kpb + ((size_t)((b*32 + kt)*8 + ft))*2048;
            #pragma unroll
            for (int ks = 0; ks < 4; ks++){
                uint4 Af[2];
                #pragma unroll
                for (int mf=0; mf<2; mf++)
                    Af[mf] = *(const uint4*)(As + ((ks*2 + mf)*32 + lane)*4);
                uint2 Bf[4];
                #pragma unroll
                for (int nf=0; nf<4; nf++)
                    Bf[nf] = *(const uint2*)(Bb + ((ks*8 + nb + nf)*32 + lane)*2);
                #pragma unroll
                for (int mf=0; mf<2; mf++)
                    #pragma unroll
                    for (int nf=0; nf<4; nf++)
                        mma_bf16(C[mf][nf], (const unsigned*)&Af[mf], (const unsigned*)&Bf[nf]);
            }
        }

        #pragma unroll
        for (int mf = 0; mf < 2; mf++)
            #pragma unroll
            for (int rh = 0; rh < 2; rh++){
                int row = qt*32 + mf*16 + g + 8*rh;
                float rs = 0.f;
                #pragma unroll
                for (int nf = 0; nf < 4; nf++){
                    float e0 = fexp(C[mf][nf][rh*2+0] * SCALE);
                    float e1 = fexp(C[mf][nf][rh*2+1] * SCALE);
                    rs += e0 + e1;
                    int kcol = kb*256 + wc*32 + nf*8 + 2*t;
                    size_t idx = ((size_t)(b*QQ + row))*KK2 + kcol;
                    ((__nv_bfloat162*)g_E)[idx >> 1] = __floats2bfloat162_rn(e0, e1);
                }
                rsl[mf][rh] += rs;
            }
    }

    #pragma unroll
    for (int mf = 0; mf < 2; mf++)
        #pragma unroll
        for (int rh = 0; rh < 2; rh++){
            float rs = rsl[mf][rh];
            rs += __shfl_xor_sync(0xffffffffu, rs, 1);
            rs += __shfl_xor_sync(0xffffffffu, rs, 2);
            if (t == 0) l_s[wc*32 + mf*16 + g + 8*rh] = rs;
        }
    __syncthreads();
    if (tid < 32){
        float s = 0.f;
        #pragma unroll
        for (int w = 0; w < 8; w++) s += l_s[w*32 + tid];
        g_linv[b*QQ + qt*32 + tid] = 1.0f / s;
    }
}

// ---------------- pass2 (fused, fp16 mma, 32-row q-tiles, 2 CTAs/SM): W in smem; O = W*V ----------------
#define WROW 36   // W row stride in 32-bit words
__global__ void __launch_bounds__(NTHREADS, 2) pass2_kernel(
    float* __restrict__ out,
    const float* __restrict__ cq, const float* __restrict__ ck,
    const unsigned char* __restrict__ am, const unsigned char* __restrict__ al,
    const float* __restrict__ bias)
{
    extern __shared__ unsigned smw[];   // 2 * 32*36 words = 9216 B
    int tid = threadIdx.x, lane = tid & 31, wc = tid >> 5;
    int g = lane >> 2, t = lane & 3;
    int b = blockIdx.x >> 6, qt = blockIdx.x & 63;
    const int q0 = qt*32;

    // build role: thread owns row brow (0..31), 8 cols at bc0 (within 64-col k-tile)
    const int brow = tid >> 3;
    const int s8   = tid & 7;
    const int bc0  = s8 * 8;
    const float2 cqv = *(const float2*)(cq + ((size_t)(b*QQ + q0 + brow))*2);
    const float li   = g_linv[b*QQ + q0 + brow];
    const size_t erow = ((size_t)(b*QQ + q0 + brow))*KK2;
    const float bsc = __ldg(bias);
    const int m32 = g_mask_is_int32;

    float C[2][8][4];
    #pragma unroll
    for (int a=0;a<2;a++)
        #pragma unroll
        for (int n=0;n<8;n++)
            #pragma unroll
            for (int c=0;c<4;c++) C[a][n][c]=0.f;

    #pragma unroll 1
    for (int kt = 0; kt < 32; kt++){
        unsigned* Wb = smw + (kt & 1) * (32*WROW);

        // ---- build W tile (32x64 fp16): 8 elems per thread ----
        {
            int cb = kt*64 + bc0;
            uint4 eu = *(const uint4*)(g_E + erow + cb);       // 8 bf16
            const unsigned* ew = (const unsigned*)&eu;
            int amv[8], alv[8];
            if (m32){
                const int4* ap = (const int4*)((const int*)am + erow + cb);
                const int4* lp = (const int4*)((const int*)al + erow + cb);
                int4 a0 = ap[0], a1 = ap[1], l0 = lp[0], l1 = lp[1];
                amv[0]=a0.x; amv[1]=a0.y; amv[2]=a0.z; amv[3]=a0.w;
                amv[4]=a1.x; amv[5]=a1.y; amv[6]=a1.z; amv[7]=a1.w;
                alv[0]=l0.x; alv[1]=l0.y; alv[2]=l0.z; alv[3]=l0.w;
                alv[4]=l1.x; alv[5]=l1.y; alv[6]=l1.z; alv[7]=l1.w;
            } else {
                uint2 au = *(const uint2*)(am + erow + cb);
                uint2 lu = *(const uint2*)(al + erow + cb);
                const unsigned char* ab = (const unsigned char*)&au;
                const unsigned char* lb = (const unsigned char*)&lu;
                #pragma unroll
                for (int c = 0; c < 8; c++){ amv[c] = ab[c]; alv[c] = lb[c]; }
            }
            float4 ck4[4];
            #pragma unroll
            for (int i = 0; i < 4; i++)
                ck4[i] = __ldg((const float4*)(ck + ((size_t)(b*KK2 + cb))*2) + i);
            const float2* ckp = (const float2*)&ck4[0];

            float wv[8];
            #pragma unroll
            for (int c = 0; c < 8; c++){
                __nv_bfloat162 e2 = *(__nv_bfloat162*)&ew[c>>1];
                float e = __bfloat162float((c & 1) ? e2.y : e2.x) * li;
                float dx = cqv.x - ckp[c].x;
                float dy = cqv.y - ckp[c].y;
                float r2 = fmaxf(dx*dx + dy*dy, 1e-30f);
                float d  = alv[c] ? 0.f : (r2 * frsqrt2(r2) * bsc);
                wv[c] = amv[c] ? 0.f : (e - d);
            }
            __half2 h0 = __floats2half2_rn(wv[0], wv[1]);
            __half2 h1 = __floats2half2_rn(wv[2], wv[3]);
            __half2 h2 = __floats2half2_rn(wv[4], wv[5]);
            __half2 h3 = __floats2half2_rn(wv[6], wv[7]);
            *(uint4*)(Wb + brow*WROW + s8*4) =
                make_uint4(*(unsigned*)&h0, *(unsigned*)&h1, *(unsigned*)&h2, *(unsigned*)&h3);
        }
        __syncthreads();

        // ---- mma fp16: A frags from Wb (4x LDS.32, conflict-free), B from g_Vph ----
        const unsigned* Bb = g_Vph + ((size_t)((b*8 + wc)*32 + kt))*2048;
        #pragma unroll
        for (int ks = 0; ks < 4; ks++){
            unsigned Af[2][4];
            #pragma unroll
            for (int mf = 0; mf < 2; mf++){
                int rowbase = (mf*16 + g)*WROW + ks*8 + t;
                Af[mf][0] = Wb[rowbase];
                Af[mf][1] = Wb[rowbase + 8*WROW];
                Af[mf][2] = Wb[rowbase + 4];
                Af[mf][3] = Wb[rowbase + 8*WROW + 4];
            }
            uint2 Bf[8];
            #pragma unroll
            for (int nf = 0; nf < 8; nf++)
                Bf[nf] = *(const uint2*)(Bb + ((ks*8 + nf)*32 + lane)*2);
            #pragma unroll
            for (int mf = 0; mf < 2; mf++)
                #pragma unroll
                for (int nf = 0; nf < 8; nf++)
                    mma_fp16(C[mf][nf], Af[mf], (const unsigned*)&Bf[nf]);
        }
        // next build writes the other buffer; sync(kt+1) transitively orders
        // mma(kt) readers before build(kt+2) rewrites this buffer.
    }

    // ---- epilogue ----
    #pragma unroll
    for (int mf = 0; mf < 2; mf++)
        #pragma unroll
        for (int rh = 0; rh < 2; rh++){
            int row = q0 + mf*16 + g + 8*rh;
            float* orow = out + ((size_t)(b*QQ + row))*FVV;
            #pragma unroll
            for (int nf = 0; nf < 8; nf++){
                int fv = wc*64 + nf*8 + 2*t;
                *(float2*)(orow + fv) = make_float2(C[mf][nf][rh*2+0], C[mf][nf][rh*2+1]);
            }
        }
}

extern "C" void kernel_launch(void* const* d_in, const int* in_sizes, int n_in,
                              void* d_out, int out_size)
{
    const float*         q    = (const float*)d_in[0];
    const float*         k    = (const float*)d_in[1];
    const float*         v    = (const float*)d_in[2];
    const float*         cq   = (const float*)d_in[3];
    const float*         ck   = (const float*)d_in[4];
    const unsigned char* am   = (const unsigned char*)d_in[5];
    const unsigned char* al   = (const unsigned char*)d_in[6];
    const float*         bias = (const float*)d_in[7];
    float*               out  = (float*)d_out;

    static int smem_set = 0;
    if (!smem_set){
        cudaFuncSetAttribute(pass1_kernel, cudaFuncAttributeMaxDynamicSharedMemorySize, 33792);
        cudaFuncSetAttribute(pass2_kernel, cudaFuncAttributeMaxDynamicSharedMemorySize, 9216);
        smem_set = 1;
    }

    detect_mask_kernel<<<1, 256>>>(am);
    prep_all_kernel<<<14336, NTHREADS>>>(q, k, v);
    pass1_kernel<<<512, NTHREADS, 33792>>>();
    pass2_kernel<<<512, NTHREADS, 9216>>>(out, cq, ck, am, al, bias);
}